// round 10
// baseline (speedup 1.0000x reference)
#include <cuda_runtime.h>
#include <cuda_fp16.h>
#include <cstdint>

#define B_  16384
#define H_  1024
#define BH_ (B_ * H_)
#define HH_ (H_ * H_)

// ---------------- device scratch ----------------
__device__ float g_k[BH_];
__device__ float g_v[BH_];
__device__ float g_r[BH_];
__device__ __half g_ah[3][BH_];   // mixed activations, fp16 hi
__device__ __half g_al[3][BH_];   // mixed activations, fp16 residual
__device__ __half g_rh[BH_];      // sigmoid(r)*wkv hi
__device__ __half g_rl[BH_];      // sigmoid(r)*wkv residual
__device__ __half g_wh[4][HH_];   // Wk,Wv,Wr,Wo fp16 (hi only)

// ---------------- PTX helpers (plain sm_103-legal) ----------------
__device__ __forceinline__ uint32_t smem_u32(const void* p) {
    uint32_t a;
    asm("{ .reg .u64 t; cvta.to.shared.u64 t, %1; cvt.u32.u64 %0, t; }" : "=r"(a) : "l"(p));
    return a;
}

#define CP16(s, g) asm volatile("cp.async.cg.shared.global [%0], [%1], 16;" :: "r"(s), "l"(g))
#define CP_COMMIT() asm volatile("cp.async.commit_group;" ::: "memory")
#define CP_WAIT(n)  asm volatile("cp.async.wait_group %0;" :: "n"(n) : "memory")

#define LDSM4(r, addr) \
    asm volatile("ldmatrix.sync.aligned.m8n8.x4.shared.b16 {%0,%1,%2,%3}, [%4];" \
        : "=r"((r)[0]), "=r"((r)[1]), "=r"((r)[2]), "=r"((r)[3]) : "r"(addr))

#define MMA16816(d, a, b) \
    asm volatile("mma.sync.aligned.m16n8k16.row.col.f32.f16.f16.f32 " \
        "{%0,%1,%2,%3}, {%4,%5,%6,%7}, {%8,%9}, {%0,%1,%2,%3};" \
        : "+f"((d)[0]), "+f"((d)[1]), "+f"((d)[2]), "+f"((d)[3]) \
        : "r"((a)[0]), "r"((a)[1]), "r"((a)[2]), "r"((a)[3]), \
          "r"((b)[0]), "r"((b)[1]))

// Conflict-free layout for 32B rows: XOR row bit2 into the 16B-chunk bit.
__device__ __forceinline__ uint32_t sw_off(int row, int chunk) {
    return (uint32_t)(row * 32 + (((chunk ^ (row >> 2)) & 1) << 4));
}

// ---------------- fp16 hi/lo split ----------------
__device__ __forceinline__ void split4h(const float4& v, uint2& hi, uint2& lo) {
    const float* f = reinterpret_cast<const float*>(&v);
    uint32_t hs[4], ls[4];
#pragma unroll
    for (int j = 0; j < 4; j++) {
        __half h = __float2half_rn(f[j]);
        __half l = __float2half_rn(f[j] - __half2float(h));
        hs[j] = (uint32_t)__half_as_ushort(h);
        ls[j] = (uint32_t)__half_as_ushort(l);
    }
    hi.x = hs[0] | (hs[1] << 16); hi.y = hs[2] | (hs[3] << 16);
    lo.x = ls[0] | (ls[1] << 16); lo.y = ls[2] | (ls[3] << 16);
}
__device__ __forceinline__ uint2 cvt4h(const float4& v) {
    const float* f = reinterpret_cast<const float*>(&v);
    uint32_t hs[4];
#pragma unroll
    for (int j = 0; j < 4; j++)
        hs[j] = (uint32_t)__half_as_ushort(__float2half_rn(f[j]));
    uint2 r;
    r.x = hs[0] | (hs[1] << 16); r.y = hs[2] | (hs[3] << 16);
    return r;
}

// ---------------- GEMM: C = (Ah+Al) @ Wh^T, fp16 2-product split ----------------
// CTA tile 128x128, BK=16, 4 warps (warp tile 64x64), 4-stage cp.async pipeline, 2 CTAs/SM.
static constexpr int STAGES     = 4;
static constexpr int OFF_AL     = 4096;               // Ah 4K | Al 4K | Bh 4K
static constexpr int OFF_BH     = 8192;
static constexpr int STG_BYTES  = 12288;
static constexpr int SMEM_BYTES = STAGES * STG_BYTES; // 49152
static constexpr int KSTEPS     = H_ / 16;            // 64

__device__ __forceinline__ void load_stage(
    uint32_t sb, int stage,
    const __half* __restrict__ ah, const __half* __restrict__ al,
    const __half* __restrict__ bh,
    int kt, int tid)
{
    const uint32_t base = sb + stage * STG_BYTES;
    // A and B: 128 rows x 2 chunks = 256 tasks each -> 2 per thread
#pragma unroll
    for (int i = 0; i < 2; ++i) {
        const int t = tid * 2 + i;
        const int r = t >> 1, c = t & 1;
        const size_t g = (size_t)r * H_ + kt + c * 8;
        const uint32_t s = base + sw_off(r, c);
        CP16(s,          ah + g);
        CP16(s + OFF_AL, al + g);
        CP16(s + OFF_BH, bh + g);
    }
}

__device__ __forceinline__ void gemm_mma(
    const __half* __restrict__ Ah, const __half* __restrict__ Al,
    const __half* __restrict__ Wh,
    float* __restrict__ C)
{
    extern __shared__ char smem[];
    const uint32_t sb = smem_u32(smem);
    const int tid  = threadIdx.x;
    const int lane = tid & 31;
    const int w    = tid >> 5;
    const int wm   = (w & 1) * 64;       // warp M offset (0/64)
    const int wn   = (w >> 1) * 64;      // warp N offset (0/64)
    const int m0   = blockIdx.y * 128;
    const int n0   = blockIdx.x * 128;

    const __half* pAh = Ah + (size_t)m0 * H_;
    const __half* pAl = Al + (size_t)m0 * H_;
    const __half* pBh = Wh + (size_t)n0 * H_;

    float acc[4][8][4];
#pragma unroll
    for (int i = 0; i < 4; i++)
#pragma unroll
        for (int j = 0; j < 8; j++)
#pragma unroll
            for (int q = 0; q < 4; q++) acc[i][j][q] = 0.0f;

#pragma unroll
    for (int s = 0; s < STAGES - 1; ++s) {
        load_stage(sb, s, pAh, pAl, pBh, s * 16, tid);
        CP_COMMIT();
    }

    const int lrow = lane & 15;
    const int lchk = lane >> 4;          // 0/1 -> 16B chunk selector

    for (int k = 0; k < KSTEPS; ++k) {
        CP_WAIT(STAGES - 2);
        __syncthreads();
        const uint32_t st = sb + (k & (STAGES - 1)) * STG_BYTES;

        // A fragments (4 m-tiles x {hi,lo})
        uint32_t ah[4][4], al[4][4];
#pragma unroll
        for (int mt = 0; mt < 4; ++mt) {
            const int row = wm + mt * 16 + lrow;
            LDSM4(ah[mt], st +          sw_off(row, lchk));
            LDSM4(al[mt], st + OFF_AL + sw_off(row, lchk));
        }
        // B fragments (8 n-tiles, hi only); each x4 covers 2 n-tiles
        uint32_t bh[8][2];
#pragma unroll
        for (int q = 0; q < 4; ++q) {
            uint32_t r[4];
            const int row = wn + q * 16 + lrow;
            LDSM4(r, st + OFF_BH + sw_off(row, lchk));
            bh[2 * q][0] = r[0]; bh[2 * q + 1][0] = r[1];
            bh[2 * q][1] = r[2]; bh[2 * q + 1][1] = r[3];
        }

        if (k + STAGES - 1 < KSTEPS)
            load_stage(sb, (k + STAGES - 1) & (STAGES - 1), pAh, pAl, pBh,
                       (k + STAGES - 1) * 16, tid);
        CP_COMMIT();

        // Product-major: long runs of independent accumulators (no RAW chains)
#pragma unroll
        for (int mt = 0; mt < 4; ++mt)
#pragma unroll
            for (int nt = 0; nt < 8; ++nt)
                MMA16816(acc[mt][nt], ah[mt], bh[nt]);
#pragma unroll
        for (int mt = 0; mt < 4; ++mt)
#pragma unroll
            for (int nt = 0; nt < 8; ++nt)
                MMA16816(acc[mt][nt], al[mt], bh[nt]);
    }

    // epilogue: fp32 direct to global
    const int er = lane >> 2;
    const int ec = (lane & 3) * 2;
#pragma unroll
    for (int mt = 0; mt < 4; ++mt) {
        const int r0 = m0 + wm + mt * 16 + er;
#pragma unroll
        for (int nt = 0; nt < 8; ++nt) {
            const int c0 = n0 + wn + nt * 8 + ec;
            float2 lo2 = make_float2(acc[mt][nt][0], acc[mt][nt][1]);
            float2 hi2 = make_float2(acc[mt][nt][2], acc[mt][nt][3]);
            *reinterpret_cast<float2*>(&C[(size_t)r0 * H_ + c0])       = lo2;
            *reinterpret_cast<float2*>(&C[(size_t)(r0 + 8) * H_ + c0]) = hi2;
        }
    }
}

__global__ void __launch_bounds__(128, 2) gemm_kvr_kernel() {
    const int z = blockIdx.z;
    float* C = (z == 0) ? g_k : (z == 1) ? g_v : g_r;
    gemm_mma(g_ah[z], g_al[z], g_wh[z], C);
}
__global__ void __launch_bounds__(128, 2) gemm_out_kernel(float* __restrict__ out) {
    gemm_mma(g_rh, g_rl, g_wh[3], out);
}

// ---------------- pointwise kernels ----------------
__global__ void __launch_bounds__(256) mix_split_kernel(
    const float* __restrict__ x, const float* __restrict__ alpha,
    const float* __restrict__ tmk, const float* __restrict__ tmv,
    const float* __restrict__ tmr)
{
    const int base = (blockIdx.x * 256 + threadIdx.x) << 2;
    const int h = base & (H_ - 1);
    const float4 xv = *reinterpret_cast<const float4*>(x + base);
    const float4 av = *reinterpret_cast<const float4*>(alpha + base);
    const float4 tms[3] = {
        *reinterpret_cast<const float4*>(tmk + h),
        *reinterpret_cast<const float4*>(tmv + h),
        *reinterpret_cast<const float4*>(tmr + h)
    };
#pragma unroll
    for (int s = 0; s < 3; ++s) {
        float4 m;
        m.x = fmaf(xv.x - av.x, tms[s].x, av.x);
        m.y = fmaf(xv.y - av.y, tms[s].y, av.y);
        m.z = fmaf(xv.z - av.z, tms[s].z, av.z);
        m.w = fmaf(xv.w - av.w, tms[s].w, av.w);
        uint2 hi, lo;
        split4h(m, hi, lo);
        *reinterpret_cast<uint2*>(&g_ah[s][base]) = hi;
        *reinterpret_cast<uint2*>(&g_al[s][base]) = lo;
    }
}

__global__ void __launch_bounds__(256) wsplit_kernel(
    const float* __restrict__ Wk, const float* __restrict__ Wv,
    const float* __restrict__ Wr, const float* __restrict__ Wo)
{
    const int w = blockIdx.y;
    const float* W = (w == 0) ? Wk : (w == 1) ? Wv : (w == 2) ? Wr : Wo;
    const int base = (blockIdx.x * 256 + threadIdx.x) << 2;
    const float4 v = *reinterpret_cast<const float4*>(W + base);
    *reinterpret_cast<uint2*>(&g_wh[w][base]) = cvt4h(v);
}

__global__ void __launch_bounds__(256) wkv_kernel(
    const float* __restrict__ x,  const float* __restrict__ aa,
    const float* __restrict__ bb, const float* __restrict__ pp,
    const float* __restrict__ td, const float* __restrict__ tf,
    float* __restrict__ out)
{
    const int base = (blockIdx.x * 256 + threadIdx.x) << 2;
    const int h = base & (H_ - 1);

    const float4 k4  = *reinterpret_cast<const float4*>(&g_k[base]);
    const float4 v4  = *reinterpret_cast<const float4*>(&g_v[base]);
    const float4 r4  = *reinterpret_cast<const float4*>(&g_r[base]);
    const float4 a4  = *reinterpret_cast<const float4*>(&aa[base]);
    const float4 b4  = *reinterpret_cast<const float4*>(&bb[base]);
    const float4 p4  = *reinterpret_cast<const float4*>(&pp[base]);
    const float4 x4  = *reinterpret_cast<const float4*>(&x[base]);
    const float4 tf4 = *reinterpret_cast<const float4*>(&tf[h]);
    const float4 td4 = *reinterpret_cast<const float4*>(&td[h]);

    float4 o_rw, o_naa, o_nbb, o_q2;
    const float* kf = (const float*)&k4;  const float* vf = (const float*)&v4;
    const float* rf = (const float*)&r4;  const float* af = (const float*)&a4;
    const float* bf = (const float*)&b4;  const float* pf = (const float*)&p4;
    const float* tff = (const float*)&tf4; const float* tdf = (const float*)&td4;
    float* rw = (float*)&o_rw; float* naa = (float*)&o_naa;
    float* nbb = (float*)&o_nbb; float* oq2 = (float*)&o_q2;

#pragma unroll
    for (int j = 0; j < 4; j++) {
        const float k = kf[j], v = vf[j], a = af[j], b = bf[j], p = pf[j];
        const float r = 1.0f / (1.0f + expf(-rf[j]));

        const float ww  = tff[j] + k;
        const float qq  = fmaxf(p, ww);
        const float e1  = expf(p - qq);
        const float e2  = expf(ww - qq);
        const float wkv = (e1 * a + e2 * v) / (e1 * b + e2);
        rw[j] = r * wkv;

        const float ww2 = p + tdf[j];
        const float q2  = fmaxf(ww2, k);
        const float e1b = expf(ww2 - q2);
        const float e2b = expf(k - q2);
        naa[j] = e1b * a + e2b * v;
        nbb[j] = e1b * b + e2b;
        oq2[j] = q2;
    }

    uint2 hi, lo;
    split4h(o_rw, hi, lo);
    *reinterpret_cast<uint2*>(&g_rh[base]) = hi;
    *reinterpret_cast<uint2*>(&g_rl[base]) = lo;

    *reinterpret_cast<float4*>(&out[(size_t)BH_ + base])     = x4;
    *reinterpret_cast<float4*>(&out[(size_t)2 * BH_ + base]) = o_naa;
    *reinterpret_cast<float4*>(&out[(size_t)3 * BH_ + base]) = o_nbb;
    *reinterpret_cast<float4*>(&out[(size_t)4 * BH_ + base]) = o_q2;
}

// ---------------- launch ----------------
extern "C" void kernel_launch(void* const* d_in, const int* in_sizes, int n_in,
                              void* d_out, int out_size)
{
    const float* x     = (const float*)d_in[0];
    const float* alpha = (const float*)d_in[1];
    const float* aa    = (const float*)d_in[2];
    const float* bb    = (const float*)d_in[3];
    const float* pp    = (const float*)d_in[4];
    const float* td    = (const float*)d_in[5];
    const float* tf    = (const float*)d_in[6];
    const float* tmk   = (const float*)d_in[7];
    const float* tmv   = (const float*)d_in[8];
    const float* tmr   = (const float*)d_in[9];
    const float* Wk    = (const float*)d_in[10];
    const float* Wv    = (const float*)d_in[11];
    const float* Wr    = (const float*)d_in[12];
    const float* Wo    = (const float*)d_in[13];
    float* out = (float*)d_out;

    cudaFuncSetAttribute(gemm_kvr_kernel, cudaFuncAttributeMaxDynamicSharedMemorySize, SMEM_BYTES);
    cudaFuncSetAttribute(gemm_out_kernel, cudaFuncAttributeMaxDynamicSharedMemorySize, SMEM_BYTES);

    wsplit_kernel<<<dim3(HH_ / 1024, 4), 256>>>(Wk, Wv, Wr, Wo);
    mix_split_kernel<<<BH_ / 1024, 256>>>(x, alpha, tmk, tmv, tmr);

    gemm_kvr_kernel<<<dim3(H_ / 128, B_ / 128, 3), 128, SMEM_BYTES>>>();

    wkv_kernel<<<BH_ / 1024, 256>>>(x, aa, bb, pp, td, tf, out);

    gemm_out_kernel<<<dim3(H_ / 128, B_ / 128, 1), 128, SMEM_BYTES>>>(out);
}

// round 12
// speedup vs baseline: 1.3133x; 1.3133x over previous
#include <cuda_runtime.h>
#include <cuda_fp16.h>
#include <cstdint>

#define B_  16384
#define H_  1024
#define BH_ (B_ * H_)
#define HH_ (H_ * H_)

// ---------------- device scratch ----------------
__device__ float g_k[BH_];
__device__ float g_v[BH_];
__device__ float g_r[BH_];
__device__ __half g_ah[3][BH_];   // mixed activations, fp16 hi
__device__ __half g_al[3][BH_];   // mixed activations, fp16 residual
__device__ __half g_rh[BH_];      // sigmoid(r)*wkv hi
__device__ __half g_rl[BH_];      // sigmoid(r)*wkv residual
__device__ __half g_wh[4][HH_];   // Wk,Wv,Wr,Wo fp16 (hi only)

// ---------------- PTX helpers (plain sm_103-legal) ----------------
__device__ __forceinline__ uint32_t smem_u32(const void* p) {
    uint32_t a;
    asm("{ .reg .u64 t; cvta.to.shared.u64 t, %1; cvt.u32.u64 %0, t; }" : "=r"(a) : "l"(p));
    return a;
}

#define CP16(s, g) asm volatile("cp.async.cg.shared.global [%0], [%1], 16;" :: "r"(s), "l"(g))
#define CP_COMMIT() asm volatile("cp.async.commit_group;" ::: "memory")
#define CP_WAIT(n)  asm volatile("cp.async.wait_group %0;" :: "n"(n) : "memory")

#define LDSM4(r, addr) \
    asm volatile("ldmatrix.sync.aligned.m8n8.x4.shared.b16 {%0,%1,%2,%3}, [%4];" \
        : "=r"((r)[0]), "=r"((r)[1]), "=r"((r)[2]), "=r"((r)[3]) : "r"(addr))

#define MMA16816(d, a, b) \
    asm volatile("mma.sync.aligned.m16n8k16.row.col.f32.f16.f16.f32 " \
        "{%0,%1,%2,%3}, {%4,%5,%6,%7}, {%8,%9}, {%0,%1,%2,%3};" \
        : "+f"((d)[0]), "+f"((d)[1]), "+f"((d)[2]), "+f"((d)[3]) \
        : "r"((a)[0]), "r"((a)[1]), "r"((a)[2]), "r"((a)[3]), \
          "r"((b)[0]), "r"((b)[1]))

// Conflict-free layout for 32B rows: XOR row bit2 into the 16B-chunk bit.
__device__ __forceinline__ uint32_t sw_off(int row, int chunk) {
    return (uint32_t)(row * 32 + (((chunk ^ (row >> 2)) & 1) << 4));
}

// ---------------- fp16 hi/lo split ----------------
__device__ __forceinline__ void split4h(const float4& v, uint2& hi, uint2& lo) {
    const float* f = reinterpret_cast<const float*>(&v);
    uint32_t hs[4], ls[4];
#pragma unroll
    for (int j = 0; j < 4; j++) {
        __half h = __float2half_rn(f[j]);
        __half l = __float2half_rn(f[j] - __half2float(h));
        hs[j] = (uint32_t)__half_as_ushort(h);
        ls[j] = (uint32_t)__half_as_ushort(l);
    }
    hi.x = hs[0] | (hs[1] << 16); hi.y = hs[2] | (hs[3] << 16);
    lo.x = ls[0] | (ls[1] << 16); lo.y = ls[2] | (ls[3] << 16);
}
__device__ __forceinline__ uint2 cvt4h(const float4& v) {
    const float* f = reinterpret_cast<const float*>(&v);
    uint32_t hs[4];
#pragma unroll
    for (int j = 0; j < 4; j++)
        hs[j] = (uint32_t)__half_as_ushort(__float2half_rn(f[j]));
    uint2 r;
    r.x = hs[0] | (hs[1] << 16); r.y = hs[2] | (hs[3] << 16);
    return r;
}

// ---------------- GEMM: C = (Ah+Al) @ Wh^T, fp16 2-product split ----------------
// CTA tile 64x256, BK=16, 8 warps (warp tile 32x64), 4-stage cp.async pipeline, 2 CTAs/SM.
static constexpr int STAGES     = 4;
static constexpr int OFF_AL     = 2048;               // Ah 2K | Al 2K | Bh 8K
static constexpr int OFF_BH     = 4096;
static constexpr int STG_BYTES  = 12288;
static constexpr int SMEM_BYTES = STAGES * STG_BYTES; // 49152
static constexpr int KSTEPS     = H_ / 16;            // 64

__device__ __forceinline__ void load_stage(
    uint32_t sb, int stage,
    const __half* __restrict__ ah, const __half* __restrict__ al,
    const __half* __restrict__ bh,
    int kt, int tid)
{
    const uint32_t base = sb + stage * STG_BYTES;
    // A: 64 rows x 2 chunks per array; tid<128 -> ah, tid>=128 -> al
    {
        const int at = tid & 127;
        const int r = at >> 1, c = at & 1;
        const size_t g = (size_t)r * H_ + kt + c * 8;
        const __half* src = (tid < 128) ? ah : al;
        const uint32_t dst = base + ((tid < 128) ? 0u : (uint32_t)OFF_AL) + sw_off(r, c);
        CP16(dst, src + g);
    }
    // B: 256 rows x 2 chunks = 512 tasks -> 2 per thread
#pragma unroll
    for (int i = 0; i < 2; ++i) {
        const int t = tid * 2 + i;
        const int r = t >> 1, c = t & 1;
        const size_t g = (size_t)r * H_ + kt + c * 8;
        CP16(base + OFF_BH + sw_off(r, c), bh + g);
    }
}

__device__ __forceinline__ void gemm_mma(
    const __half* __restrict__ Ah, const __half* __restrict__ Al,
    const __half* __restrict__ Wh,
    float* __restrict__ C)
{
    extern __shared__ char smem[];
    const uint32_t sb = smem_u32(smem);
    const int tid  = threadIdx.x;
    const int lane = tid & 31;
    const int w    = tid >> 5;
    const int wm   = (w & 1) * 32;       // warp M offset (0/32)
    const int wn   = (w >> 1) * 64;      // warp N offset (0/64/128/192)
    const int m0   = blockIdx.y * 64;
    const int n0   = blockIdx.x * 256;

    const __half* pAh = Ah + (size_t)m0 * H_;
    const __half* pAl = Al + (size_t)m0 * H_;
    const __half* pBh = Wh + (size_t)n0 * H_;

    float acc[2][8][4];
#pragma unroll
    for (int i = 0; i < 2; i++)
#pragma unroll
        for (int j = 0; j < 8; j++)
#pragma unroll
            for (int q = 0; q < 4; q++) acc[i][j][q] = 0.0f;

#pragma unroll
    for (int s = 0; s < STAGES - 1; ++s) {
        load_stage(sb, s, pAh, pAl, pBh, s * 16, tid);
        CP_COMMIT();
    }

    const int lrow = lane & 15;
    const int lchk = lane >> 4;          // 0/1 -> 16B chunk selector

    for (int k = 0; k < KSTEPS; ++k) {
        CP_WAIT(STAGES - 2);
        __syncthreads();
        const uint32_t st = sb + (k & (STAGES - 1)) * STG_BYTES;

        // A fragments (2 m-tiles x {hi,lo})
        uint32_t ah[2][4], al[2][4];
#pragma unroll
        for (int mt = 0; mt < 2; ++mt) {
            const int row = wm + mt * 16 + lrow;
            LDSM4(ah[mt], st +          sw_off(row, lchk));
            LDSM4(al[mt], st + OFF_AL + sw_off(row, lchk));
        }
        // B fragments (8 n-tiles, hi only); each x4 covers 2 n-tiles
        uint32_t bh[8][2];
#pragma unroll
        for (int q = 0; q < 4; ++q) {
            uint32_t r[4];
            const int row = wn + q * 16 + lrow;
            LDSM4(r, st + OFF_BH + sw_off(row, lchk));
            bh[2 * q][0] = r[0]; bh[2 * q + 1][0] = r[1];
            bh[2 * q][1] = r[2]; bh[2 * q + 1][1] = r[3];
        }

        if (k + STAGES - 1 < KSTEPS)
            load_stage(sb, (k + STAGES - 1) & (STAGES - 1), pAh, pAl, pBh,
                       (k + STAGES - 1) * 16, tid);
        CP_COMMIT();

        // Product-major: consecutive MMAs hit distinct accumulators (no RAW chains)
#pragma unroll
        for (int mt = 0; mt < 2; ++mt)
#pragma unroll
            for (int nt = 0; nt < 8; ++nt)
                MMA16816(acc[mt][nt], ah[mt], bh[nt]);
#pragma unroll
        for (int mt = 0; mt < 2; ++mt)
#pragma unroll
            for (int nt = 0; nt < 8; ++nt)
                MMA16816(acc[mt][nt], al[mt], bh[nt]);
    }

    // epilogue: fp32 direct to global
    const int er = lane >> 2;
    const int ec = (lane & 3) * 2;
#pragma unroll
    for (int mt = 0; mt < 2; ++mt) {
        const int r0 = m0 + wm + mt * 16 + er;
#pragma unroll
        for (int nt = 0; nt < 8; ++nt) {
            const int c0 = n0 + wn + nt * 8 + ec;
            float2 lo2 = make_float2(acc[mt][nt][0], acc[mt][nt][1]);
            float2 hi2 = make_float2(acc[mt][nt][2], acc[mt][nt][3]);
            *reinterpret_cast<float2*>(&C[(size_t)r0 * H_ + c0])       = lo2;
            *reinterpret_cast<float2*>(&C[(size_t)(r0 + 8) * H_ + c0]) = hi2;
        }
    }
}

__global__ void __launch_bounds__(256, 2) gemm_kvr_kernel() {
    const int z = blockIdx.z;
    float* C = (z == 0) ? g_k : (z == 1) ? g_v : g_r;
    gemm_mma(g_ah[z], g_al[z], g_wh[z], C);
}
__global__ void __launch_bounds__(256, 2) gemm_out_kernel(float* __restrict__ out) {
    gemm_mma(g_rh, g_rl, g_wh[3], out);
}

// ---------------- pointwise kernels ----------------
__global__ void __launch_bounds__(256) mix_split_kernel(
    const float* __restrict__ x, const float* __restrict__ alpha,
    const float* __restrict__ tmk, const float* __restrict__ tmv,
    const float* __restrict__ tmr)
{
    const int base = (blockIdx.x * 256 + threadIdx.x) << 2;
    const int h = base & (H_ - 1);
    const float4 xv = *reinterpret_cast<const float4*>(x + base);
    const float4 av = *reinterpret_cast<const float4*>(alpha + base);
    const float4 tms[3] = {
        *reinterpret_cast<const float4*>(tmk + h),
        *reinterpret_cast<const float4*>(tmv + h),
        *reinterpret_cast<const float4*>(tmr + h)
    };
#pragma unroll
    for (int s = 0; s < 3; ++s) {
        float4 m;
        m.x = fmaf(xv.x - av.x, tms[s].x, av.x);
        m.y = fmaf(xv.y - av.y, tms[s].y, av.y);
        m.z = fmaf(xv.z - av.z, tms[s].z, av.z);
        m.w = fmaf(xv.w - av.w, tms[s].w, av.w);
        uint2 hi, lo;
        split4h(m, hi, lo);
        *reinterpret_cast<uint2*>(&g_ah[s][base]) = hi;
        *reinterpret_cast<uint2*>(&g_al[s][base]) = lo;
    }
}

__global__ void __launch_bounds__(256) wsplit_kernel(
    const float* __restrict__ Wk, const float* __restrict__ Wv,
    const float* __restrict__ Wr, const float* __restrict__ Wo)
{
    const int w = blockIdx.y;
    const float* W = (w == 0) ? Wk : (w == 1) ? Wv : (w == 2) ? Wr : Wo;
    const int base = (blockIdx.x * 256 + threadIdx.x) << 2;
    const float4 v = *reinterpret_cast<const float4*>(W + base);
    *reinterpret_cast<uint2*>(&g_wh[w][base]) = cvt4h(v);
}

__global__ void __launch_bounds__(256) wkv_kernel(
    const float* __restrict__ x,  const float* __restrict__ aa,
    const float* __restrict__ bb, const float* __restrict__ pp,
    const float* __restrict__ td, const float* __restrict__ tf,
    float* __restrict__ out)
{
    const int base = (blockIdx.x * 256 + threadIdx.x) << 2;
    const int h = base & (H_ - 1);

    const float4 k4  = *reinterpret_cast<const float4*>(&g_k[base]);
    const float4 v4  = *reinterpret_cast<const float4*>(&g_v[base]);
    const float4 r4  = *reinterpret_cast<const float4*>(&g_r[base]);
    const float4 a4  = *reinterpret_cast<const float4*>(&aa[base]);
    const float4 b4  = *reinterpret_cast<const float4*>(&bb[base]);
    const float4 p4  = *reinterpret_cast<const float4*>(&pp[base]);
    const float4 x4  = *reinterpret_cast<const float4*>(&x[base]);
    const float4 tf4 = *reinterpret_cast<const float4*>(&tf[h]);
    const float4 td4 = *reinterpret_cast<const float4*>(&td[h]);

    float4 o_rw, o_naa, o_nbb, o_q2;
    const float* kf = (const float*)&k4;  const float* vf = (const float*)&v4;
    const float* rf = (const float*)&r4;  const float* af = (const float*)&a4;
    const float* bf = (const float*)&b4;  const float* pf = (const float*)&p4;
    const float* tff = (const float*)&tf4; const float* tdf = (const float*)&td4;
    float* rw = (float*)&o_rw; float* naa = (float*)&o_naa;
    float* nbb = (float*)&o_nbb; float* oq2 = (float*)&o_q2;

#pragma unroll
    for (int j = 0; j < 4; j++) {
        const float k = kf[j], v = vf[j], a = af[j], b = bf[j], p = pf[j];
        const float r = 1.0f / (1.0f + expf(-rf[j]));

        const float ww  = tff[j] + k;
        const float qq  = fmaxf(p, ww);
        const float e1  = expf(p - qq);
        const float e2  = expf(ww - qq);
        const float wkv = (e1 * a + e2 * v) / (e1 * b + e2);
        rw[j] = r * wkv;

        const float ww2 = p + tdf[j];
        const float q2  = fmaxf(ww2, k);
        const float e1b = expf(ww2 - q2);
        const float e2b = expf(k - q2);
        naa[j] = e1b * a + e2b * v;
        nbb[j] = e1b * b + e2b;
        oq2[j] = q2;
    }

    uint2 hi, lo;
    split4h(o_rw, hi, lo);
    *reinterpret_cast<uint2*>(&g_rh[base]) = hi;
    *reinterpret_cast<uint2*>(&g_rl[base]) = lo;

    *reinterpret_cast<float4*>(&out[(size_t)BH_ + base])     = x4;
    *reinterpret_cast<float4*>(&out[(size_t)2 * BH_ + base]) = o_naa;
    *reinterpret_cast<float4*>(&out[(size_t)3 * BH_ + base]) = o_nbb;
    *reinterpret_cast<float4*>(&out[(size_t)4 * BH_ + base]) = o_q2;
}

// ---------------- launch ----------------
extern "C" void kernel_launch(void* const* d_in, const int* in_sizes, int n_in,
                              void* d_out, int out_size)
{
    const float* x     = (const float*)d_in[0];
    const float* alpha = (const float*)d_in[1];
    const float* aa    = (const float*)d_in[2];
    const float* bb    = (const float*)d_in[3];
    const float* pp    = (const float*)d_in[4];
    const float* td    = (const float*)d_in[5];
    const float* tf    = (const float*)d_in[6];
    const float* tmk   = (const float*)d_in[7];
    const float* tmv   = (const float*)d_in[8];
    const float* tmr   = (const float*)d_in[9];
    const float* Wk    = (const float*)d_in[10];
    const float* Wv    = (const float*)d_in[11];
    const float* Wr    = (const float*)d_in[12];
    const float* Wo    = (const float*)d_in[13];
    float* out = (float*)d_out;

    cudaFuncSetAttribute(gemm_kvr_kernel, cudaFuncAttributeMaxDynamicSharedMemorySize, SMEM_BYTES);
    cudaFuncSetAttribute(gemm_out_kernel, cudaFuncAttributeMaxDynamicSharedMemorySize, SMEM_BYTES);

    wsplit_kernel<<<dim3(HH_ / 1024, 4), 256>>>(Wk, Wv, Wr, Wo);
    mix_split_kernel<<<BH_ / 1024, 256>>>(x, alpha, tmk, tmv, tmr);

    gemm_kvr_kernel<<<dim3(H_ / 256, B_ / 64, 3), 256, SMEM_BYTES>>>();

    wkv_kernel<<<BH_ / 1024, 256>>>(x, aa, bb, pp, td, tf, out);

    gemm_out_kernel<<<dim3(H_ / 256, B_ / 64, 1), 256, SMEM_BYTES>>>(out);
}